// round 1
// baseline (speedup 1.0000x reference)
#include <cuda_runtime.h>
#include <math.h>

// PA-MPJPE loss: batched similarity (Procrustes) alignment of target onto output,
// then mean over (N,K) of pointwise L2 residual norm.
//
// Per sample (p = target row, q = output row, K=133 points):
//   mu1 = mean p, mu2 = mean q, X1 = p - mu1, X2 = q - mu2
//   M[a][b] = sum_k X1_a X2_b   (3x3 cross covariance = reference's K)
//   Optimal proper rotation via Horn quaternion method: largest eigenpair of 4x4 N(M).
//   lambda_max = tr(R_opt M); scale = lambda_max / sum|X1|^2
//   residual_k = X2_k - scale * R * X1_k;  per-sample loss = mean_k ||residual_k||

#define KPTS 133
#define FLOATS_PER (3 * KPTS)   // 399
#define WARPS_PER_BLK 8
#define BLK_THREADS (WARPS_PER_BLK * 32)
#define NSAMP_MAX 65536

__device__ float g_loss[NSAMP_MAX];

__device__ __forceinline__ float wreduce(float v) {
#pragma unroll
    for (int o = 16; o > 0; o >>= 1) v += __shfl_xor_sync(0xffffffffu, v, o);
    return v;
}

__device__ __forceinline__ float det3(float a, float b, float c,
                                      float d, float e, float f,
                                      float g, float h, float i) {
    return a * (e * i - f * h) - b * (d * i - f * g) + c * (d * h - e * g);
}

__global__ __launch_bounds__(BLK_THREADS)
void pampjpe_kernel(const float* __restrict__ outp,   // (N,K,3) "output"
                    const float* __restrict__ tgt,    // (N,K,3) "target"
                    int nsamp) {
    // per-warp staged point data: [warp][0]=target, [warp][1]=output
    __shared__ float sh[WARPS_PER_BLK][2][FLOATS_PER + 1];
    __shared__ float sSums[WARPS_PER_BLK][16];   // reduced sums per sample
    __shared__ float sRes[WARPS_PER_BLK][10];    // scale + R (row major)

    const int w = threadIdx.x >> 5;
    const int lane = threadIdx.x & 31;
    const int samp = blockIdx.x * WARPS_PER_BLK + w;
    const bool active = (samp < nsamp);

    // ---- stage points coalesced into SMEM (one warp per sample) ----
    if (active) {
        const float* pt = tgt  + (size_t)samp * FLOATS_PER;
        const float* po = outp + (size_t)samp * FLOATS_PER;
        for (int i = lane; i < FLOATS_PER; i += 32) {
            sh[w][0][i] = pt[i];
            sh[w][1][i] = po[i];
        }
    }
    __syncwarp();

    // ---- phase A: accumulate 16 sums ----
    float Sp0 = 0.f, Sp1 = 0.f, Sp2 = 0.f;
    float Sq0 = 0.f, Sq1 = 0.f, Sq2 = 0.f;
    float Spp = 0.f;
    float M00 = 0.f, M01 = 0.f, M02 = 0.f;
    float M10 = 0.f, M11 = 0.f, M12 = 0.f;
    float M20 = 0.f, M21 = 0.f, M22 = 0.f;

    if (active) {
        for (int k = lane; k < KPTS; k += 32) {
            float px = sh[w][0][3 * k + 0];
            float py = sh[w][0][3 * k + 1];
            float pz = sh[w][0][3 * k + 2];
            float qx = sh[w][1][3 * k + 0];
            float qy = sh[w][1][3 * k + 1];
            float qz = sh[w][1][3 * k + 2];
            Sp0 += px; Sp1 += py; Sp2 += pz;
            Sq0 += qx; Sq1 += qy; Sq2 += qz;
            Spp += px * px + py * py + pz * pz;
            M00 += px * qx; M01 += px * qy; M02 += px * qz;
            M10 += py * qx; M11 += py * qy; M12 += py * qz;
            M20 += pz * qx; M21 += pz * qy; M22 += pz * qz;
        }
    }
    // butterfly reductions (all lanes end with totals)
    Sp0 = wreduce(Sp0); Sp1 = wreduce(Sp1); Sp2 = wreduce(Sp2);
    Sq0 = wreduce(Sq0); Sq1 = wreduce(Sq1); Sq2 = wreduce(Sq2);
    Spp = wreduce(Spp);
    M00 = wreduce(M00); M01 = wreduce(M01); M02 = wreduce(M02);
    M10 = wreduce(M10); M11 = wreduce(M11); M12 = wreduce(M12);
    M20 = wreduce(M20); M21 = wreduce(M21); M22 = wreduce(M22);

    if (lane == 0) {
        float* d = sSums[w];
        d[0] = Sp0; d[1] = Sp1; d[2] = Sp2;
        d[3] = Sq0; d[4] = Sq1; d[5] = Sq2;
        d[6] = Spp;
        d[7] = M00;  d[8] = M01;  d[9] = M02;
        d[10] = M10; d[11] = M11; d[12] = M12;
        d[13] = M20; d[14] = M21; d[15] = M22;
    }
    __syncthreads();

    // ---- phase B: one solver thread per sample in this block ----
    if (threadIdx.x < WARPS_PER_BLK &&
        (blockIdx.x * WARPS_PER_BLK + (int)threadIdx.x) < nsamp) {
        const float* d = sSums[threadIdx.x];
        const float invK = 1.0f / (float)KPTS;
        float sp0 = d[0], sp1 = d[1], sp2 = d[2];
        float sq0 = d[3], sq1 = d[4], sq2 = d[5];
        float spp = d[6];
        // centered cross covariance
        float Sxx = d[7]  - sp0 * sq0 * invK;
        float Sxy = d[8]  - sp0 * sq1 * invK;
        float Sxz = d[9]  - sp0 * sq2 * invK;
        float Syx = d[10] - sp1 * sq0 * invK;
        float Syy = d[11] - sp1 * sq1 * invK;
        float Syz = d[12] - sp1 * sq2 * invK;
        float Szx = d[13] - sp2 * sq0 * invK;
        float Szy = d[14] - sp2 * sq1 * invK;
        float Szz = d[15] - sp2 * sq2 * invK;
        float var1 = spp - (sp0 * sp0 + sp1 * sp1 + sp2 * sp2) * invK;

        // Horn's 4x4 symmetric matrix (q ~= R p)
        float N00 = Sxx + Syy + Szz;
        float N01 = Syz - Szy;
        float N02 = Szx - Sxz;
        float N03 = Sxy - Syx;
        float N11 = Sxx - Syy - Szz;
        float N12 = Sxy + Syx;
        float N13 = Szx + Sxz;
        float N22 = -Sxx + Syy - Szz;
        float N23 = Syz + Szy;
        float N33 = -Sxx - Syy + Szz;

        // B = N^2 (symmetric)
        float B00 = N00*N00 + N01*N01 + N02*N02 + N03*N03;
        float B01 = N00*N01 + N01*N11 + N02*N12 + N03*N13;
        float B02 = N00*N02 + N01*N12 + N02*N22 + N03*N23;
        float B03 = N00*N03 + N01*N13 + N02*N23 + N03*N33;
        float B11 = N01*N01 + N11*N11 + N12*N12 + N13*N13;
        float B12 = N01*N02 + N11*N12 + N12*N22 + N13*N23;
        float B13 = N01*N03 + N11*N13 + N12*N23 + N13*N33;
        float B22 = N02*N02 + N12*N12 + N22*N22 + N23*N23;
        float B23 = N02*N03 + N12*N13 + N22*N23 + N23*N33;
        float B33 = N03*N03 + N13*N13 + N23*N23 + N33*N33;

        // power sums -> characteristic quartic x^4 + C2 x^2 + C1 x + C0 (trace N = 0)
        float p2 = B00 + B11 + B22 + B33;
        float p3 = B00*N00 + B11*N11 + B22*N22 + B33*N33
                 + 2.0f * (B01*N01 + B02*N02 + B03*N03 + B12*N12 + B13*N13 + B23*N23);
        float p4 = B00*B00 + B11*B11 + B22*B22 + B33*B33
                 + 2.0f * (B01*B01 + B02*B02 + B03*B03 + B12*B12 + B13*B13 + B23*B23);
        float C2 = -0.5f * p2;
        float C1 = -p3 * (1.0f / 3.0f);
        float C0 = 0.25f * (0.5f * p2 * p2 - p4);

        // Newton from upper bound lambda0 = sqrt(p2) >= lambda_max (monotone)
        float lam = sqrtf(fmaxf(p2, 0.0f));
#pragma unroll
        for (int it = 0; it < 12; ++it) {
            float lam2 = lam * lam;
            float f  = ((lam2 + C2) * lam + C1) * lam + C0;
            float fp = (4.0f * lam2 + 2.0f * C2) * lam + C1;
            fp = (fabsf(fp) < 1e-30f) ? 1e-30f : fp;
            lam -= f / fp;
        }

        // eigenvector from adjugate of A = N - lam I (symmetric)
        float a00 = N00 - lam, a01 = N01, a02 = N02, a03 = N03;
        float a11 = N11 - lam, a12 = N12, a13 = N13;
        float a22 = N22 - lam, a23 = N23;
        float a33 = N33 - lam;

        float adj00 = det3(a11, a12, a13, a12, a22, a23, a13, a23, a33);
        float adj11 = det3(a00, a02, a03, a02, a22, a23, a03, a23, a33);
        float adj22 = det3(a00, a01, a03, a01, a11, a13, a03, a13, a33);
        float adj33 = det3(a00, a01, a02, a01, a11, a12, a02, a12, a22);
        float adj01 = -det3(a01, a02, a03, a12, a22, a23, a13, a23, a33);
        float adj02 =  det3(a01, a02, a03, a11, a12, a13, a13, a23, a33);
        float adj03 = -det3(a01, a02, a03, a11, a12, a13, a12, a22, a23);
        float adj12 = -det3(a00, a02, a03, a01, a12, a13, a03, a23, a33);
        float adj13 =  det3(a00, a02, a03, a01, a12, a13, a02, a22, a23);
        float adj23 = -det3(a00, a01, a03, a01, a11, a13, a02, a12, a23);

        // choose adjugate row with largest diagonal magnitude
        float v0, v1, v2, v3;
        float b0 = fabsf(adj00), b1 = fabsf(adj11), b2 = fabsf(adj22), b3 = fabsf(adj33);
        if (b0 >= b1 && b0 >= b2 && b0 >= b3) {
            v0 = adj00; v1 = adj01; v2 = adj02; v3 = adj03;
        } else if (b1 >= b2 && b1 >= b3) {
            v0 = adj01; v1 = adj11; v2 = adj12; v3 = adj13;
        } else if (b2 >= b3) {
            v0 = adj02; v1 = adj12; v2 = adj22; v3 = adj23;
        } else {
            v0 = adj03; v1 = adj13; v2 = adj23; v3 = adj33;
        }
        float n2 = v0 * v0 + v1 * v1 + v2 * v2 + v3 * v3;
        float qw, qx, qy, qz;
        if (n2 > 1e-30f) {
            float inv = rsqrtf(n2);
            qw = v0 * inv; qx = v1 * inv; qy = v2 * inv; qz = v3 * inv;
        } else {
            qw = 1.0f; qx = 0.0f; qy = 0.0f; qz = 0.0f;
        }

        // rotation from quaternion (maps p -> q)
        float R00 = qw*qw + qx*qx - qy*qy - qz*qz;
        float R01 = 2.0f * (qx*qy - qw*qz);
        float R02 = 2.0f * (qx*qz + qw*qy);
        float R10 = 2.0f * (qx*qy + qw*qz);
        float R11 = qw*qw - qx*qx + qy*qy - qz*qz;
        float R12 = 2.0f * (qy*qz - qw*qx);
        float R20 = 2.0f * (qx*qz - qw*qy);
        float R21 = 2.0f * (qy*qz + qw*qx);
        float R22 = qw*qw - qx*qx - qy*qy + qz*qz;

        float scale = lam / fmaxf(var1, 1e-30f);

        float* r = sRes[threadIdx.x];
        r[0] = scale;
        r[1] = R00; r[2] = R01; r[3] = R02;
        r[4] = R10; r[5] = R11; r[6] = R12;
        r[7] = R20; r[8] = R21; r[9] = R22;
    }
    __syncthreads();

    // ---- phase C: residual norms ----
    if (active) {
        const float invK = 1.0f / (float)KPTS;
        const float* r = sRes[w];
        float sc  = r[0];
        float R00 = r[1], R01 = r[2], R02 = r[3];
        float R10 = r[4], R11 = r[5], R12 = r[6];
        float R20 = r[7], R21 = r[8], R22 = r[9];
        float mu1x = Sp0 * invK, mu1y = Sp1 * invK, mu1z = Sp2 * invK;
        float mu2x = Sq0 * invK, mu2y = Sq1 * invK, mu2z = Sq2 * invK;

        float acc = 0.0f;
        for (int k = lane; k < KPTS; k += 32) {
            float px = sh[w][0][3 * k + 0] - mu1x;
            float py = sh[w][0][3 * k + 1] - mu1y;
            float pz = sh[w][0][3 * k + 2] - mu1z;
            float qx = sh[w][1][3 * k + 0] - mu2x;
            float qy = sh[w][1][3 * k + 1] - mu2y;
            float qz = sh[w][1][3 * k + 2] - mu2z;
            float rx = qx - sc * (R00 * px + R01 * py + R02 * pz);
            float ry = qy - sc * (R10 * px + R11 * py + R12 * pz);
            float rz = qz - sc * (R20 * px + R21 * py + R22 * pz);
            acc += sqrtf(rx * rx + ry * ry + rz * rz);
        }
        acc = wreduce(acc);
        if (lane == 0) g_loss[samp] = acc * invK;
    }
}

__global__ void final_reduce_kernel(float* __restrict__ out, int nsamp) {
    __shared__ double shd[256];
    double acc = 0.0;
    for (int i = threadIdx.x; i < nsamp; i += 256) acc += (double)g_loss[i];
    shd[threadIdx.x] = acc;
    __syncthreads();
#pragma unroll
    for (int s = 128; s > 0; s >>= 1) {
        if (threadIdx.x < s) shd[threadIdx.x] += shd[threadIdx.x + s];
        __syncthreads();
    }
    if (threadIdx.x == 0) out[0] = (float)(shd[0] / (double)nsamp);
}

extern "C" void kernel_launch(void* const* d_in, const int* in_sizes, int n_in,
                              void* d_out, int out_size) {
    const float* outp = (const float*)d_in[0];   // "output"
    const float* tgt  = (const float*)d_in[1];   // "target"
    int nsamp = in_sizes[0] / FLOATS_PER;
    int blocks = (nsamp + WARPS_PER_BLK - 1) / WARPS_PER_BLK;
    pampjpe_kernel<<<blocks, BLK_THREADS>>>(outp, tgt, nsamp);
    final_reduce_kernel<<<1, 256>>>((float*)d_out, nsamp);
}

// round 4
// speedup vs baseline: 1.4847x; 1.4847x over previous
#include <cuda_runtime.h>
#include <math.h>

// PA-MPJPE loss, 3-pass design (resubmission — prior benches hit broker infra
// failures before the kernel ever ran):
//  pass1: per-sample 16 reduction sums (warp/sample, direct stride-3 loads)
//  pass2: per-sample Procrustes solve (Horn quaternion, thread/sample)
//  pass3: per-sample residual norms (warp/sample) -> per-block partial
//  pass4: deterministic final reduce

#define KPTS 133
#define FLOATS_PER (3 * KPTS)   // 399
#define WARPS_PER_BLK 8
#define BLK_THREADS (WARPS_PER_BLK * 32)
#define NSAMP_MAX 65536

__device__ float4 g_sums[NSAMP_MAX * 4];    // 16 floats per sample
__device__ float4 g_params[NSAMP_MAX * 4];  // scale,mu1,mu2,R per sample
__device__ float  g_part[(NSAMP_MAX + WARPS_PER_BLK - 1) / WARPS_PER_BLK];

__device__ __forceinline__ float wreduce(float v) {
#pragma unroll
    for (int o = 16; o > 0; o >>= 1) v += __shfl_xor_sync(0xffffffffu, v, o);
    return v;
}

__device__ __forceinline__ float det3(float a, float b, float c,
                                      float d, float e, float f,
                                      float g, float h, float i) {
    return a * (e * i - f * h) - b * (d * i - f * g) + c * (d * h - e * g);
}

// ---------------- pass 1: sums ----------------
__global__ __launch_bounds__(BLK_THREADS)
void sums_kernel(const float* __restrict__ outp,
                 const float* __restrict__ tgt, int nsamp) {
    const int w = threadIdx.x >> 5;
    const int lane = threadIdx.x & 31;
    const int samp = blockIdx.x * WARPS_PER_BLK + w;
    if (samp >= nsamp) return;

    const float* __restrict__ p = tgt  + (size_t)samp * FLOATS_PER;
    const float* __restrict__ q = outp + (size_t)samp * FLOATS_PER;

    // gather all points for this lane (zero-padded; zeros don't perturb sums)
    float px[5], py[5], pz[5], qx[5], qy[5], qz[5];
#pragma unroll
    for (int j = 0; j < 5; ++j) {
        int k = lane + 32 * j;
        bool v = (k < KPTS);
        int b = 3 * k;
        px[j] = v ? p[b + 0] : 0.f;
        py[j] = v ? p[b + 1] : 0.f;
        pz[j] = v ? p[b + 2] : 0.f;
        qx[j] = v ? q[b + 0] : 0.f;
        qy[j] = v ? q[b + 1] : 0.f;
        qz[j] = v ? q[b + 2] : 0.f;
    }

    float Sp0 = 0.f, Sp1 = 0.f, Sp2 = 0.f;
    float Sq0 = 0.f, Sq1 = 0.f, Sq2 = 0.f;
    float Spp = 0.f;
    float M00 = 0.f, M01 = 0.f, M02 = 0.f;
    float M10 = 0.f, M11 = 0.f, M12 = 0.f;
    float M20 = 0.f, M21 = 0.f, M22 = 0.f;
#pragma unroll
    for (int j = 0; j < 5; ++j) {
        Sp0 += px[j]; Sp1 += py[j]; Sp2 += pz[j];
        Sq0 += qx[j]; Sq1 += qy[j]; Sq2 += qz[j];
        Spp += px[j]*px[j] + py[j]*py[j] + pz[j]*pz[j];
        M00 += px[j]*qx[j]; M01 += px[j]*qy[j]; M02 += px[j]*qz[j];
        M10 += py[j]*qx[j]; M11 += py[j]*qy[j]; M12 += py[j]*qz[j];
        M20 += pz[j]*qx[j]; M21 += pz[j]*qy[j]; M22 += pz[j]*qz[j];
    }

    Sp0 = wreduce(Sp0); Sp1 = wreduce(Sp1); Sp2 = wreduce(Sp2);
    Sq0 = wreduce(Sq0); Sq1 = wreduce(Sq1); Sq2 = wreduce(Sq2);
    Spp = wreduce(Spp);
    M00 = wreduce(M00); M01 = wreduce(M01); M02 = wreduce(M02);
    M10 = wreduce(M10); M11 = wreduce(M11); M12 = wreduce(M12);
    M20 = wreduce(M20); M21 = wreduce(M21); M22 = wreduce(M22);

    if (lane == 0) {
        float4* dst = &g_sums[(size_t)samp * 4];
        dst[0] = make_float4(Sp0, Sp1, Sp2, Sq0);
        dst[1] = make_float4(Sq1, Sq2, Spp, M00);
        dst[2] = make_float4(M01, M02, M10, M11);
        dst[3] = make_float4(M12, M20, M21, M22);
    }
}

// ---------------- pass 2: solver ----------------
__global__ __launch_bounds__(256)
void solver_kernel(int nsamp) {
    int t = blockIdx.x * blockDim.x + threadIdx.x;
    if (t >= nsamp) return;

    const float4* s = &g_sums[(size_t)t * 4];
    float4 s0 = s[0], s1 = s[1], s2 = s[2], s3 = s[3];
    float sp0 = s0.x, sp1 = s0.y, sp2 = s0.z;
    float sq0 = s0.w, sq1 = s1.x, sq2 = s1.y;
    float spp = s1.z;
    const float invK = 1.0f / (float)KPTS;

    float Sxx = s1.w - sp0 * sq0 * invK;
    float Sxy = s2.x - sp0 * sq1 * invK;
    float Sxz = s2.y - sp0 * sq2 * invK;
    float Syx = s2.z - sp1 * sq0 * invK;
    float Syy = s2.w - sp1 * sq1 * invK;
    float Syz = s3.x - sp1 * sq2 * invK;
    float Szx = s3.y - sp2 * sq0 * invK;
    float Szy = s3.z - sp2 * sq1 * invK;
    float Szz = s3.w - sp2 * sq2 * invK;
    float var1 = spp - (sp0*sp0 + sp1*sp1 + sp2*sp2) * invK;

    float N00 = Sxx + Syy + Szz;
    float N01 = Syz - Szy;
    float N02 = Szx - Sxz;
    float N03 = Sxy - Syx;
    float N11 = Sxx - Syy - Szz;
    float N12 = Sxy + Syx;
    float N13 = Szx + Sxz;
    float N22 = -Sxx + Syy - Szz;
    float N23 = Syz + Szy;
    float N33 = -Sxx - Syy + Szz;

    float B00 = N00*N00 + N01*N01 + N02*N02 + N03*N03;
    float B01 = N00*N01 + N01*N11 + N02*N12 + N03*N13;
    float B02 = N00*N02 + N01*N12 + N02*N22 + N03*N23;
    float B03 = N00*N03 + N01*N13 + N02*N23 + N03*N33;
    float B11 = N01*N01 + N11*N11 + N12*N12 + N13*N13;
    float B12 = N01*N02 + N11*N12 + N12*N22 + N13*N23;
    float B13 = N01*N03 + N11*N13 + N12*N23 + N13*N33;
    float B22 = N02*N02 + N12*N12 + N22*N22 + N23*N23;
    float B23 = N02*N03 + N12*N13 + N22*N23 + N23*N33;
    float B33 = N03*N03 + N13*N13 + N23*N23 + N33*N33;

    float p2 = B00 + B11 + B22 + B33;
    float p3 = B00*N00 + B11*N11 + B22*N22 + B33*N33
             + 2.0f * (B01*N01 + B02*N02 + B03*N03 + B12*N12 + B13*N13 + B23*N23);
    float p4 = B00*B00 + B11*B11 + B22*B22 + B33*B33
             + 2.0f * (B01*B01 + B02*B02 + B03*B03 + B12*B12 + B13*B13 + B23*B23);
    float C2 = -0.5f * p2;
    float C1 = -p3 * (1.0f / 3.0f);
    float C0 = 0.25f * (0.5f * p2 * p2 - p4);

    float lam = sqrtf(fmaxf(p2, 0.0f));
#pragma unroll
    for (int it = 0; it < 12; ++it) {
        float lam2 = lam * lam;
        float f  = ((lam2 + C2) * lam + C1) * lam + C0;
        float fp = (4.0f * lam2 + 2.0f * C2) * lam + C1;
        fp = (fabsf(fp) < 1e-30f) ? 1e-30f : fp;
        lam -= f / fp;
    }

    float a00 = N00 - lam, a01 = N01, a02 = N02, a03 = N03;
    float a11 = N11 - lam, a12 = N12, a13 = N13;
    float a22 = N22 - lam, a23 = N23;
    float a33 = N33 - lam;

    float adj00 = det3(a11, a12, a13, a12, a22, a23, a13, a23, a33);
    float adj11 = det3(a00, a02, a03, a02, a22, a23, a03, a23, a33);
    float adj22 = det3(a00, a01, a03, a01, a11, a13, a03, a13, a33);
    float adj33 = det3(a00, a01, a02, a01, a11, a12, a02, a12, a22);
    float adj01 = -det3(a01, a02, a03, a12, a22, a23, a13, a23, a33);
    float adj02 =  det3(a01, a02, a03, a11, a12, a13, a13, a23, a33);
    float adj03 = -det3(a01, a02, a03, a11, a12, a13, a12, a22, a23);
    float adj12 = -det3(a00, a02, a03, a01, a12, a13, a03, a23, a33);
    float adj13 =  det3(a00, a02, a03, a01, a12, a13, a02, a22, a23);
    float adj23 = -det3(a00, a01, a03, a01, a11, a13, a02, a12, a23);

    float v0, v1, v2, v3;
    float b0 = fabsf(adj00), b1 = fabsf(adj11), b2 = fabsf(adj22), b3 = fabsf(adj33);
    if (b0 >= b1 && b0 >= b2 && b0 >= b3) {
        v0 = adj00; v1 = adj01; v2 = adj02; v3 = adj03;
    } else if (b1 >= b2 && b1 >= b3) {
        v0 = adj01; v1 = adj11; v2 = adj12; v3 = adj13;
    } else if (b2 >= b3) {
        v0 = adj02; v1 = adj12; v2 = adj22; v3 = adj23;
    } else {
        v0 = adj03; v1 = adj13; v2 = adj23; v3 = adj33;
    }
    float n2 = v0*v0 + v1*v1 + v2*v2 + v3*v3;
    float qw, qx, qy, qz;
    if (n2 > 1e-30f) {
        float inv = rsqrtf(n2);
        qw = v0 * inv; qx = v1 * inv; qy = v2 * inv; qz = v3 * inv;
    } else {
        qw = 1.0f; qx = 0.0f; qy = 0.0f; qz = 0.0f;
    }

    float R00 = qw*qw + qx*qx - qy*qy - qz*qz;
    float R01 = 2.0f * (qx*qy - qw*qz);
    float R02 = 2.0f * (qx*qz + qw*qy);
    float R10 = 2.0f * (qx*qy + qw*qz);
    float R11 = qw*qw - qx*qx + qy*qy - qz*qz;
    float R12 = 2.0f * (qy*qz - qw*qx);
    float R20 = 2.0f * (qx*qz - qw*qy);
    float R21 = 2.0f * (qy*qz + qw*qx);
    float R22 = qw*qw - qx*qx - qy*qy + qz*qz;

    float scale = lam / fmaxf(var1, 1e-30f);

    float4* dst = &g_params[(size_t)t * 4];
    dst[0] = make_float4(scale, sp0 * invK, sp1 * invK, sp2 * invK);
    dst[1] = make_float4(sq0 * invK, sq1 * invK, sq2 * invK, R00);
    dst[2] = make_float4(R01, R02, R10, R11);
    dst[3] = make_float4(R12, R20, R21, R22);
}

// ---------------- pass 3: residuals ----------------
__global__ __launch_bounds__(BLK_THREADS)
void resid_kernel(const float* __restrict__ outp,
                  const float* __restrict__ tgt, int nsamp) {
    __shared__ float sloss[WARPS_PER_BLK];

    const int w = threadIdx.x >> 5;
    const int lane = threadIdx.x & 31;
    const int samp = blockIdx.x * WARPS_PER_BLK + w;
    const bool active = (samp < nsamp);

    float acc = 0.0f;
    if (active) {
        const float4* pr = &g_params[(size_t)samp * 4];
        float4 r0 = pr[0], r1 = pr[1], r2v = pr[2], r3 = pr[3];
        float sc = r0.x;
        float mu1x = r0.y, mu1y = r0.z, mu1z = r0.w;
        float mu2x = r1.x, mu2y = r1.y, mu2z = r1.z;
        float R00 = r1.w, R01 = r2v.x, R02 = r2v.y;
        float R10 = r2v.z, R11 = r2v.w, R12 = r3.x;
        float R20 = r3.y, R21 = r3.z, R22 = r3.w;

        const float* __restrict__ p = tgt  + (size_t)samp * FLOATS_PER;
        const float* __restrict__ q = outp + (size_t)samp * FLOATS_PER;

#pragma unroll
        for (int j = 0; j < 5; ++j) {
            int k = lane + 32 * j;
            bool v = (k < KPTS);
            int b = 3 * k;
            float px = v ? p[b + 0] : 0.f;
            float py = v ? p[b + 1] : 0.f;
            float pz = v ? p[b + 2] : 0.f;
            float qx = v ? q[b + 0] : 0.f;
            float qy = v ? q[b + 1] : 0.f;
            float qz = v ? q[b + 2] : 0.f;
            px -= mu1x; py -= mu1y; pz -= mu1z;
            qx -= mu2x; qy -= mu2y; qz -= mu2z;
            float rx = qx - sc * (R00 * px + R01 * py + R02 * pz);
            float ry = qy - sc * (R10 * px + R11 * py + R12 * pz);
            float rz = qz - sc * (R20 * px + R21 * py + R22 * pz);
            float d2 = rx * rx + ry * ry + rz * rz;
            float nrm = (d2 > 0.f) ? d2 * rsqrtf(d2) : 0.f;
            acc += v ? nrm : 0.f;
        }
    }
    acc = wreduce(acc);
    if (lane == 0) sloss[w] = active ? acc * (1.0f / (float)KPTS) : 0.0f;
    __syncthreads();

    // warp 0 reduces the 8 per-warp partials
    if (threadIdx.x < 32) {
        float v = (lane < WARPS_PER_BLK) ? sloss[lane] : 0.0f;
#pragma unroll
        for (int o = 4; o > 0; o >>= 1) v += __shfl_xor_sync(0xffffffffu, v, o);
        if (lane == 0) g_part[blockIdx.x] = v;
    }
}

// ---------------- pass 4: final reduce ----------------
__global__ __launch_bounds__(1024)
void final_kernel(float* __restrict__ out, int nparts, int nsamp) {
    __shared__ double shd[1024];
    double acc = 0.0;
    for (int i = threadIdx.x; i < nparts; i += 1024) acc += (double)g_part[i];
    shd[threadIdx.x] = acc;
    __syncthreads();
#pragma unroll
    for (int s = 512; s > 0; s >>= 1) {
        if (threadIdx.x < s) shd[threadIdx.x] += shd[threadIdx.x + s];
        __syncthreads();
    }
    if (threadIdx.x == 0) out[0] = (float)(shd[0] / (double)nsamp);
}

extern "C" void kernel_launch(void* const* d_in, const int* in_sizes, int n_in,
                              void* d_out, int out_size) {
    const float* outp = (const float*)d_in[0];   // "output"
    const float* tgt  = (const float*)d_in[1];   // "target"
    int nsamp = in_sizes[0] / FLOATS_PER;
    int blocks = (nsamp + WARPS_PER_BLK - 1) / WARPS_PER_BLK;

    sums_kernel<<<blocks, BLK_THREADS>>>(outp, tgt, nsamp);
    solver_kernel<<<(nsamp + 255) / 256, 256>>>(nsamp);
    resid_kernel<<<blocks, BLK_THREADS>>>(outp, tgt, nsamp);
    final_kernel<<<1, 1024>>>((float*)d_out, blocks, nsamp);
}

// round 6
// speedup vs baseline: 1.7621x; 1.1868x over previous
#include <cuda_runtime.h>
#include <math.h>

// PA-MPJPE loss — single-read fused design (resubmission; prior round hit a
// broker infra failure before the kernel ran):
//  One kernel, warp-per-sample, NO cross-warp dependencies:
//   1) warp stages its sample's 2x399 floats into SMEM (coalesced)
//   2) 16 reduction sums via stride-3 LDS (conflict-free) + butterfly
//   3) ALL 32 lanes redundantly solve the 4x4 Horn eigenproblem in lockstep
//      (zero barriers, zero broadcast — costs one warp instruction stream)
//   4) residual norms from the SMEM-resident points (input read exactly once)
//   5) per-block partial -> tiny deterministic final reduce
// vs the 3-pass version this halves DRAM traffic (209MB vs 418MB).

#define KPTS 133
#define FLOATS_PER (3 * KPTS)   // 399
#define WARPS_PER_BLK 8
#define BLK_THREADS (WARPS_PER_BLK * 32)
#define NSAMP_MAX 65536

__device__ float g_part[(NSAMP_MAX + WARPS_PER_BLK - 1) / WARPS_PER_BLK];

__device__ __forceinline__ float wreduce(float v) {
#pragma unroll
    for (int o = 16; o > 0; o >>= 1) v += __shfl_xor_sync(0xffffffffu, v, o);
    return v;
}

__device__ __forceinline__ float det3(float a, float b, float c,
                                      float d, float e, float f,
                                      float g, float h, float i) {
    return a * (e * i - f * h) - b * (d * i - f * g) + c * (d * h - e * g);
}

__global__ __launch_bounds__(BLK_THREADS)
void pampjpe_fused(const float* __restrict__ outp,   // (N,K,3) "output"
                   const float* __restrict__ tgt,    // (N,K,3) "target"
                   int nsamp) {
    // per-warp staging: [warp][0]=target(p), [warp][1]=output(q)
    __shared__ float sh[WARPS_PER_BLK][2][FLOATS_PER + 1];
    __shared__ float sloss[WARPS_PER_BLK];

    const int w = threadIdx.x >> 5;
    const int lane = threadIdx.x & 31;
    const int samp = blockIdx.x * WARPS_PER_BLK + w;
    const bool active = (samp < nsamp);

    // ---- stage points (coalesced; warp-private, so only __syncwarp) ----
    if (active) {
        const float* __restrict__ p = tgt  + (size_t)samp * FLOATS_PER;
        const float* __restrict__ q = outp + (size_t)samp * FLOATS_PER;
#pragma unroll
        for (int j = 0; j < 13; ++j) {          // 13*32 = 416 >= 399
            int i = lane + 32 * j;
            if (j < 12 || i < FLOATS_PER) {
                sh[w][0][i] = p[i];
                sh[w][1][i] = q[i];
            }
        }
    }
    __syncwarp();

    // ---- 16 reduction sums ----
    float Sp0 = 0.f, Sp1 = 0.f, Sp2 = 0.f;
    float Sq0 = 0.f, Sq1 = 0.f, Sq2 = 0.f;
    float Spp = 0.f;
    float M00 = 0.f, M01 = 0.f, M02 = 0.f;
    float M10 = 0.f, M11 = 0.f, M12 = 0.f;
    float M20 = 0.f, M21 = 0.f, M22 = 0.f;

    if (active) {
#pragma unroll
        for (int j = 0; j < 5; ++j) {
            int k = lane + 32 * j;
            if (k < KPTS) {
                float px = sh[w][0][3 * k + 0];
                float py = sh[w][0][3 * k + 1];
                float pz = sh[w][0][3 * k + 2];
                float qx = sh[w][1][3 * k + 0];
                float qy = sh[w][1][3 * k + 1];
                float qz = sh[w][1][3 * k + 2];
                Sp0 += px; Sp1 += py; Sp2 += pz;
                Sq0 += qx; Sq1 += qy; Sq2 += qz;
                Spp += px * px + py * py + pz * pz;
                M00 += px * qx; M01 += px * qy; M02 += px * qz;
                M10 += py * qx; M11 += py * qy; M12 += py * qz;
                M20 += pz * qx; M21 += pz * qy; M22 += pz * qz;
            }
        }
    }
    Sp0 = wreduce(Sp0); Sp1 = wreduce(Sp1); Sp2 = wreduce(Sp2);
    Sq0 = wreduce(Sq0); Sq1 = wreduce(Sq1); Sq2 = wreduce(Sq2);
    Spp = wreduce(Spp);
    M00 = wreduce(M00); M01 = wreduce(M01); M02 = wreduce(M02);
    M10 = wreduce(M10); M11 = wreduce(M11); M12 = wreduce(M12);
    M20 = wreduce(M20); M21 = wreduce(M21); M22 = wreduce(M22);

    // ---- redundant in-warp Procrustes solve (all lanes, lockstep) ----
    const float invK = 1.0f / (float)KPTS;
    float Sxx = M00 - Sp0 * Sq0 * invK;
    float Sxy = M01 - Sp0 * Sq1 * invK;
    float Sxz = M02 - Sp0 * Sq2 * invK;
    float Syx = M10 - Sp1 * Sq0 * invK;
    float Syy = M11 - Sp1 * Sq1 * invK;
    float Syz = M12 - Sp1 * Sq2 * invK;
    float Szx = M20 - Sp2 * Sq0 * invK;
    float Szy = M21 - Sp2 * Sq1 * invK;
    float Szz = M22 - Sp2 * Sq2 * invK;
    float var1 = Spp - (Sp0 * Sp0 + Sp1 * Sp1 + Sp2 * Sp2) * invK;

    float N00 = Sxx + Syy + Szz;
    float N01 = Syz - Szy;
    float N02 = Szx - Sxz;
    float N03 = Sxy - Syx;
    float N11 = Sxx - Syy - Szz;
    float N12 = Sxy + Syx;
    float N13 = Szx + Sxz;
    float N22 = -Sxx + Syy - Szz;
    float N23 = Syz + Szy;
    float N33 = -Sxx - Syy + Szz;

    float B00 = N00*N00 + N01*N01 + N02*N02 + N03*N03;
    float B01 = N00*N01 + N01*N11 + N02*N12 + N03*N13;
    float B02 = N00*N02 + N01*N12 + N02*N22 + N03*N23;
    float B03 = N00*N03 + N01*N13 + N02*N23 + N03*N33;
    float B11 = N01*N01 + N11*N11 + N12*N12 + N13*N13;
    float B12 = N01*N02 + N11*N12 + N12*N22 + N13*N23;
    float B13 = N01*N03 + N11*N13 + N12*N23 + N13*N33;
    float B22 = N02*N02 + N12*N12 + N22*N22 + N23*N23;
    float B23 = N02*N03 + N12*N13 + N22*N23 + N23*N33;
    float B33 = N03*N03 + N13*N13 + N23*N23 + N33*N33;

    float p2 = B00 + B11 + B22 + B33;
    float p3 = B00*N00 + B11*N11 + B22*N22 + B33*N33
             + 2.0f * (B01*N01 + B02*N02 + B03*N03 + B12*N12 + B13*N13 + B23*N23);
    float p4 = B00*B00 + B11*B11 + B22*B22 + B33*B33
             + 2.0f * (B01*B01 + B02*B02 + B03*B03 + B12*B12 + B13*B13 + B23*B23);
    float C2 = -0.5f * p2;
    float C1 = -p3 * (1.0f / 3.0f);
    float C0 = 0.25f * (0.5f * p2 * p2 - p4);

    // Newton from upper bound sqrt(p2) >= lambda_max (monotone decreasing)
    float lam = sqrtf(fmaxf(p2, 0.0f));
#pragma unroll
    for (int it = 0; it < 10; ++it) {
        float lam2 = lam * lam;
        float f  = ((lam2 + C2) * lam + C1) * lam + C0;
        float fp = (4.0f * lam2 + 2.0f * C2) * lam + C1;
        fp = (fabsf(fp) < 1e-30f) ? 1e-30f : fp;
        lam -= __fdividef(f, fp);
    }

    float a00 = N00 - lam, a01 = N01, a02 = N02, a03 = N03;
    float a11 = N11 - lam, a12 = N12, a13 = N13;
    float a22 = N22 - lam, a23 = N23;
    float a33 = N33 - lam;

    float adj00 = det3(a11, a12, a13, a12, a22, a23, a13, a23, a33);
    float adj11 = det3(a00, a02, a03, a02, a22, a23, a03, a23, a33);
    float adj22 = det3(a00, a01, a03, a01, a11, a13, a03, a13, a33);
    float adj33 = det3(a00, a01, a02, a01, a11, a12, a02, a12, a22);
    float adj01 = -det3(a01, a02, a03, a12, a22, a23, a13, a23, a33);
    float adj02 =  det3(a01, a02, a03, a11, a12, a13, a13, a23, a33);
    float adj03 = -det3(a01, a02, a03, a11, a12, a13, a12, a22, a23);
    float adj12 = -det3(a00, a02, a03, a01, a12, a13, a03, a23, a33);
    float adj13 =  det3(a00, a02, a03, a01, a12, a13, a02, a22, a23);
    float adj23 = -det3(a00, a01, a03, a01, a11, a13, a02, a12, a23);

    float v0, v1, v2, v3;
    float b0 = fabsf(adj00), b1 = fabsf(adj11), b2 = fabsf(adj22), b3 = fabsf(adj33);
    if (b0 >= b1 && b0 >= b2 && b0 >= b3) {
        v0 = adj00; v1 = adj01; v2 = adj02; v3 = adj03;
    } else if (b1 >= b2 && b1 >= b3) {
        v0 = adj01; v1 = adj11; v2 = adj12; v3 = adj13;
    } else if (b2 >= b3) {
        v0 = adj02; v1 = adj12; v2 = adj22; v3 = adj23;
    } else {
        v0 = adj03; v1 = adj13; v2 = adj23; v3 = adj33;
    }
    float n2 = v0 * v0 + v1 * v1 + v2 * v2 + v3 * v3;
    float qw, qx, qy, qz;
    if (n2 > 1e-30f) {
        float inv = rsqrtf(n2);
        qw = v0 * inv; qx = v1 * inv; qy = v2 * inv; qz = v3 * inv;
    } else {
        qw = 1.0f; qx = 0.0f; qy = 0.0f; qz = 0.0f;
    }

    float R00 = qw*qw + qx*qx - qy*qy - qz*qz;
    float R01 = 2.0f * (qx*qy - qw*qz);
    float R02 = 2.0f * (qx*qz + qw*qy);
    float R10 = 2.0f * (qx*qy + qw*qz);
    float R11 = qw*qw - qx*qx + qy*qy - qz*qz;
    float R12 = 2.0f * (qy*qz - qw*qx);
    float R20 = 2.0f * (qx*qz - qw*qy);
    float R21 = 2.0f * (qy*qz + qw*qx);
    float R22 = qw*qw - qx*qx - qy*qy + qz*qz;

    float sc = lam / fmaxf(var1, 1e-30f);
    float mu1x = Sp0 * invK, mu1y = Sp1 * invK, mu1z = Sp2 * invK;
    float mu2x = Sq0 * invK, mu2y = Sq1 * invK, mu2z = Sq2 * invK;

    // ---- residual norms from SMEM-resident points ----
    float acc = 0.0f;
    if (active) {
#pragma unroll
        for (int j = 0; j < 5; ++j) {
            int k = lane + 32 * j;
            if (k < KPTS) {
                float px = sh[w][0][3 * k + 0] - mu1x;
                float py = sh[w][0][3 * k + 1] - mu1y;
                float pz = sh[w][0][3 * k + 2] - mu1z;
                float qx = sh[w][1][3 * k + 0] - mu2x;
                float qy = sh[w][1][3 * k + 1] - mu2y;
                float qz = sh[w][1][3 * k + 2] - mu2z;
                float rx = qx - sc * (R00 * px + R01 * py + R02 * pz);
                float ry = qy - sc * (R10 * px + R11 * py + R12 * pz);
                float rz = qz - sc * (R20 * px + R21 * py + R22 * pz);
                float d2 = rx * rx + ry * ry + rz * rz;
                acc += (d2 > 0.f) ? d2 * rsqrtf(d2) : 0.f;
            }
        }
    }
    acc = wreduce(acc);
    if (lane == 0) sloss[w] = active ? acc * invK : 0.0f;
    __syncthreads();

    // warp 0 combines the 8 per-warp partials
    if (threadIdx.x < 32) {
        float v = (lane < WARPS_PER_BLK) ? sloss[lane] : 0.0f;
#pragma unroll
        for (int o = 4; o > 0; o >>= 1) v += __shfl_xor_sync(0xffffffffu, v, o);
        if (lane == 0) g_part[blockIdx.x] = v;
    }
}

__global__ __launch_bounds__(1024)
void final_kernel(float* __restrict__ out, int nparts, int nsamp) {
    __shared__ double shd[1024];
    float facc = 0.0f;
    for (int i = threadIdx.x; i < nparts; i += 1024) facc += g_part[i];
    shd[threadIdx.x] = (double)facc;
    __syncthreads();
#pragma unroll
    for (int s = 512; s > 0; s >>= 1) {
        if (threadIdx.x < s) shd[threadIdx.x] += shd[threadIdx.x + s];
        __syncthreads();
    }
    if (threadIdx.x == 0) out[0] = (float)(shd[0] / (double)nsamp);
}

extern "C" void kernel_launch(void* const* d_in, const int* in_sizes, int n_in,
                              void* d_out, int out_size) {
    const float* outp = (const float*)d_in[0];   // "output"
    const float* tgt  = (const float*)d_in[1];   // "target"
    int nsamp = in_sizes[0] / FLOATS_PER;
    int blocks = (nsamp + WARPS_PER_BLK - 1) / WARPS_PER_BLK;

    pampjpe_fused<<<blocks, BLK_THREADS>>>(outp, tgt, nsamp);
    final_kernel<<<1, 1024>>>((float*)d_out, blocks, nsamp);
}

// round 7
// speedup vs baseline: 1.8626x; 1.0570x over previous
#include <cuda_runtime.h>
#include <math.h>

// PA-MPJPE loss — single-kernel, single-read design.
//  warp-per-sample:
//   1) phase A: stride-3 global loads -> registers AND SMEM (one pass);
//      16 per-lane partial sums
//   2) SMEM transpose reduction of the 16 sums (replaces 160-shuffle butterfly)
//   3) all 32 lanes redundantly solve the 4x4 Horn eigenproblem in lockstep
//   4) phase C: residual norms from SMEM-resident points (q - Rs*p - t form)
//   5) per-block partial; LAST block (atomic ticket) does the deterministic
//      fixed-order final reduction -> d_out. No second kernel.

#define KPTS 133
#define FLOATS_PER (3 * KPTS)   // 399
#define WARPS_PER_BLK 8
#define BLK_THREADS (WARPS_PER_BLK * 32)
#define NSAMP_MAX 65536
#define NPART_MAX ((NSAMP_MAX + WARPS_PER_BLK - 1) / WARPS_PER_BLK)

__device__ float g_part[NPART_MAX];
__device__ unsigned int g_count = 0;

__device__ __forceinline__ float det3(float a, float b, float c,
                                      float d, float e, float f,
                                      float g, float h, float i) {
    return a * (e * i - f * h) - b * (d * i - f * g) + c * (d * h - e * g);
}

__global__ __launch_bounds__(BLK_THREADS)
void pampjpe_fused(const float* __restrict__ outp,   // (N,K,3) "output" (q)
                   const float* __restrict__ tgt,    // (N,K,3) "target" (p)
                   float* __restrict__ d_out,
                   int nsamp) {
    // per-warp point staging: [warp][0]=p, [warp][1]=q
    __shared__ float sh[WARPS_PER_BLK][2][FLOATS_PER + 1];
    // per-warp reduction scratch: 16 sums x 32 lanes + pad col 32 for totals
    __shared__ float red[WARPS_PER_BLK][16][33];
    __shared__ float sloss[WARPS_PER_BLK];
    __shared__ unsigned int s_ticket;
    __shared__ double shd[BLK_THREADS];

    const int w = threadIdx.x >> 5;
    const int lane = threadIdx.x & 31;
    const int samp = blockIdx.x * WARPS_PER_BLK + w;
    const bool active = (samp < nsamp);

    // ---- phase A: load -> registers + SMEM, accumulate 16 partials ----
    float part[16];
#pragma unroll
    for (int s = 0; s < 16; ++s) part[s] = 0.0f;

    if (active) {
        const float* __restrict__ p = tgt  + (size_t)samp * FLOATS_PER;
        const float* __restrict__ q = outp + (size_t)samp * FLOATS_PER;
#pragma unroll
        for (int j = 0; j < 5; ++j) {
            int k = lane + 32 * j;
            if (k < KPTS) {
                int b = 3 * k;
                float px = p[b + 0], py = p[b + 1], pz = p[b + 2];
                float qx = q[b + 0], qy = q[b + 1], qz = q[b + 2];
                sh[w][0][b + 0] = px; sh[w][0][b + 1] = py; sh[w][0][b + 2] = pz;
                sh[w][1][b + 0] = qx; sh[w][1][b + 1] = qy; sh[w][1][b + 2] = qz;
                part[0] += px; part[1] += py; part[2] += pz;
                part[3] += qx; part[4] += qy; part[5] += qz;
                part[6] += px * px + py * py + pz * pz;
                part[7]  += px * qx; part[8]  += px * qy; part[9]  += px * qz;
                part[10] += py * qx; part[11] += py * qy; part[12] += py * qz;
                part[13] += pz * qx; part[14] += pz * qy; part[15] += pz * qz;
            }
        }
    }

    // ---- SMEM transpose reduction (conflict-free by (s+lane)%32 banking) ----
#pragma unroll
    for (int s = 0; s < 16; ++s) red[w][s][lane] = part[s];
    __syncwarp();
    {
        int s = lane & 15;
        int h = lane >> 4;
        float t = 0.0f;
#pragma unroll
        for (int j = 0; j < 16; ++j) t += red[w][s][h * 16 + j];
        t += __shfl_xor_sync(0xffffffffu, t, 16);
        if (lane < 16) red[w][s][32] = t;   // totals in pad column
    }
    __syncwarp();
    float tot[16];
#pragma unroll
    for (int s = 0; s < 16; ++s) tot[s] = red[w][s][32];  // broadcast reads

    const float Sp0 = tot[0], Sp1 = tot[1], Sp2 = tot[2];
    const float Sq0 = tot[3], Sq1 = tot[4], Sq2 = tot[5];
    const float Spp = tot[6];

    // ---- redundant in-warp Procrustes solve (lockstep, all lanes) ----
    const float invK = 1.0f / (float)KPTS;
    float Sxx = tot[7]  - Sp0 * Sq0 * invK;
    float Sxy = tot[8]  - Sp0 * Sq1 * invK;
    float Sxz = tot[9]  - Sp0 * Sq2 * invK;
    float Syx = tot[10] - Sp1 * Sq0 * invK;
    float Syy = tot[11] - Sp1 * Sq1 * invK;
    float Syz = tot[12] - Sp1 * Sq2 * invK;
    float Szx = tot[13] - Sp2 * Sq0 * invK;
    float Szy = tot[14] - Sp2 * Sq1 * invK;
    float Szz = tot[15] - Sp2 * Sq2 * invK;
    float var1 = Spp - (Sp0 * Sp0 + Sp1 * Sp1 + Sp2 * Sp2) * invK;

    float N00 = Sxx + Syy + Szz;
    float N01 = Syz - Szy;
    float N02 = Szx - Sxz;
    float N03 = Sxy - Syx;
    float N11 = Sxx - Syy - Szz;
    float N12 = Sxy + Syx;
    float N13 = Szx + Sxz;
    float N22 = -Sxx + Syy - Szz;
    float N23 = Syz + Szy;
    float N33 = -Sxx - Syy + Szz;

    float B00 = N00*N00 + N01*N01 + N02*N02 + N03*N03;
    float B01 = N00*N01 + N01*N11 + N02*N12 + N03*N13;
    float B02 = N00*N02 + N01*N12 + N02*N22 + N03*N23;
    float B03 = N00*N03 + N01*N13 + N02*N23 + N03*N33;
    float B11 = N01*N01 + N11*N11 + N12*N12 + N13*N13;
    float B12 = N01*N02 + N11*N12 + N12*N22 + N13*N23;
    float B13 = N01*N03 + N11*N13 + N12*N23 + N13*N33;
    float B22 = N02*N02 + N12*N12 + N22*N22 + N23*N23;
    float B23 = N02*N03 + N12*N13 + N22*N23 + N23*N33;
    float B33 = N03*N03 + N13*N13 + N23*N23 + N33*N33;

    float p2 = B00 + B11 + B22 + B33;
    float p3 = B00*N00 + B11*N11 + B22*N22 + B33*N33
             + 2.0f * (B01*N01 + B02*N02 + B03*N03 + B12*N12 + B13*N13 + B23*N23);
    float p4 = B00*B00 + B11*B11 + B22*B22 + B33*B33
             + 2.0f * (B01*B01 + B02*B02 + B03*B03 + B12*B12 + B13*B13 + B23*B23);
    float C2 = -0.5f * p2;
    float C1 = -p3 * (1.0f / 3.0f);
    float C0 = 0.25f * (0.5f * p2 * p2 - p4);

    // Newton from upper bound sqrt(p2) >= lambda_max (monotone decreasing)
    float lam = sqrtf(fmaxf(p2, 0.0f));
#pragma unroll
    for (int it = 0; it < 10; ++it) {
        float lam2 = lam * lam;
        float f  = ((lam2 + C2) * lam + C1) * lam + C0;
        float fp = (4.0f * lam2 + 2.0f * C2) * lam + C1;
        fp = (fabsf(fp) < 1e-30f) ? 1e-30f : fp;
        lam -= __fdividef(f, fp);
    }

    float a00 = N00 - lam, a01 = N01, a02 = N02, a03 = N03;
    float a11 = N11 - lam, a12 = N12, a13 = N13;
    float a22 = N22 - lam, a23 = N23;
    float a33 = N33 - lam;

    float adj00 = det3(a11, a12, a13, a12, a22, a23, a13, a23, a33);
    float adj11 = det3(a00, a02, a03, a02, a22, a23, a03, a23, a33);
    float adj22 = det3(a00, a01, a03, a01, a11, a13, a03, a13, a33);
    float adj33 = det3(a00, a01, a02, a01, a11, a12, a02, a12, a22);
    float adj01 = -det3(a01, a02, a03, a12, a22, a23, a13, a23, a33);
    float adj02 =  det3(a01, a02, a03, a11, a12, a13, a13, a23, a33);
    float adj03 = -det3(a01, a02, a03, a11, a12, a13, a12, a22, a23);
    float adj12 = -det3(a00, a02, a03, a01, a12, a13, a03, a23, a33);
    float adj13 =  det3(a00, a02, a03, a01, a12, a13, a02, a22, a23);
    float adj23 = -det3(a00, a01, a03, a01, a11, a13, a02, a12, a23);

    float v0, v1, v2, v3;
    float b0 = fabsf(adj00), b1 = fabsf(adj11), b2 = fabsf(adj22), b3 = fabsf(adj33);
    if (b0 >= b1 && b0 >= b2 && b0 >= b3) {
        v0 = adj00; v1 = adj01; v2 = adj02; v3 = adj03;
    } else if (b1 >= b2 && b1 >= b3) {
        v0 = adj01; v1 = adj11; v2 = adj12; v3 = adj13;
    } else if (b2 >= b3) {
        v0 = adj02; v1 = adj12; v2 = adj22; v3 = adj23;
    } else {
        v0 = adj03; v1 = adj13; v2 = adj23; v3 = adj33;
    }
    float n2 = v0 * v0 + v1 * v1 + v2 * v2 + v3 * v3;
    float qw, qx, qy, qz;
    if (n2 > 1e-30f) {
        float inv = rsqrtf(n2);
        qw = v0 * inv; qx = v1 * inv; qy = v2 * inv; qz = v3 * inv;
    } else {
        qw = 1.0f; qx = 0.0f; qy = 0.0f; qz = 0.0f;
    }

    float R00 = qw*qw + qx*qx - qy*qy - qz*qz;
    float R01 = 2.0f * (qx*qy - qw*qz);
    float R02 = 2.0f * (qx*qz + qw*qy);
    float R10 = 2.0f * (qx*qy + qw*qz);
    float R11 = qw*qw - qx*qx + qy*qy - qz*qz;
    float R12 = 2.0f * (qy*qz - qw*qx);
    float R20 = 2.0f * (qx*qz - qw*qy);
    float R21 = 2.0f * (qy*qz + qw*qx);
    float R22 = qw*qw - qx*qx - qy*qy + qz*qz;

    float sc = lam / fmaxf(var1, 1e-30f);
    // fold scale into R, fold means into a translation t:
    float Rs00 = sc * R00, Rs01 = sc * R01, Rs02 = sc * R02;
    float Rs10 = sc * R10, Rs11 = sc * R11, Rs12 = sc * R12;
    float Rs20 = sc * R20, Rs21 = sc * R21, Rs22 = sc * R22;
    float mu1x = Sp0 * invK, mu1y = Sp1 * invK, mu1z = Sp2 * invK;
    float mu2x = Sq0 * invK, mu2y = Sq1 * invK, mu2z = Sq2 * invK;
    float tx = mu2x - (Rs00 * mu1x + Rs01 * mu1y + Rs02 * mu1z);
    float ty = mu2y - (Rs10 * mu1x + Rs11 * mu1y + Rs12 * mu1z);
    float tz = mu2z - (Rs20 * mu1x + Rs21 * mu1y + Rs22 * mu1z);

    // ---- phase C: residual norms from SMEM points: r = q - Rs*p - t ----
    float acc = 0.0f;
    if (active) {
#pragma unroll
        for (int j = 0; j < 5; ++j) {
            int k = lane + 32 * j;
            if (k < KPTS) {
                int b = 3 * k;
                float px = sh[w][0][b + 0];
                float py = sh[w][0][b + 1];
                float pz = sh[w][0][b + 2];
                float rx = sh[w][1][b + 0] - (Rs00 * px + Rs01 * py + Rs02 * pz) - tx;
                float ry = sh[w][1][b + 1] - (Rs10 * px + Rs11 * py + Rs12 * pz) - ty;
                float rz = sh[w][1][b + 2] - (Rs20 * px + Rs21 * py + Rs22 * pz) - tz;
                float d2 = rx * rx + ry * ry + rz * rz;
                acc += (d2 > 0.f) ? d2 * rsqrtf(d2) : 0.f;
            }
        }
    }
#pragma unroll
    for (int o = 16; o > 0; o >>= 1) acc += __shfl_xor_sync(0xffffffffu, acc, o);
    if (lane == 0) sloss[w] = active ? acc * invK : 0.0f;
    __syncthreads();

    // warp 0 combines the 8 per-warp partials -> per-block partial
    if (threadIdx.x < 32) {
        float v = (lane < WARPS_PER_BLK) ? sloss[lane] : 0.0f;
#pragma unroll
        for (int o = 4; o > 0; o >>= 1) v += __shfl_xor_sync(0xffffffffu, v, o);
        if (lane == 0) g_part[blockIdx.x] = v;
    }

    // ---- last block does the deterministic final reduction ----
    if (threadIdx.x == 0) {
        __threadfence();
        s_ticket = atomicAdd(&g_count, 1u);
    }
    __syncthreads();
    if (s_ticket == gridDim.x - 1) {
        const int nparts = gridDim.x;
        double dacc = 0.0;
        for (int i = threadIdx.x; i < nparts; i += BLK_THREADS)
            dacc += (double)g_part[i];
        shd[threadIdx.x] = dacc;
        __syncthreads();
#pragma unroll
        for (int s = BLK_THREADS / 2; s > 0; s >>= 1) {
            if (threadIdx.x < s) shd[threadIdx.x] += shd[threadIdx.x + s];
            __syncthreads();
        }
        if (threadIdx.x == 0) {
            d_out[0] = (float)(shd[0] / (double)nsamp);
            g_count = 0;   // self-reset for next graph replay
        }
    }
}

extern "C" void kernel_launch(void* const* d_in, const int* in_sizes, int n_in,
                              void* d_out, int out_size) {
    const float* outp = (const float*)d_in[0];   // "output"
    const float* tgt  = (const float*)d_in[1];   // "target"
    int nsamp = in_sizes[0] / FLOATS_PER;
    int blocks = (nsamp + WARPS_PER_BLK - 1) / WARPS_PER_BLK;

    pampjpe_fused<<<blocks, BLK_THREADS>>>(outp, tgt, (float*)d_out, nsamp);
}